// round 4
// baseline (speedup 1.0000x reference)
#include <cuda_runtime.h>
#include <stdint.h>

// Problem constants (match reference)
#define N_ELEMS   4194304        // total elements
#define NUM_IDS   262144
#define M_CAP     (NUM_IDS + 1)  // 262145 output rows
#define L_CAP     128
#define OUT_TOTAL (M_CAP + M_CAP * L_CAP)   // 33,816,705 floats
#define NW        264193         // full 128-float windows (NW*128 = OUT_TOTAL-1)

// Scan decomposition: 1024 blocks * 4096 elems; 256 threads * 16 items/thread
#define NB        1024
#define EPB       4096
#define BLK       256
#define IPT       16

// Scratch (device globals: no allocation allowed) — SoA layout
__device__ __align__(16) int   g_start[M_CAP];  // start element index of run s
__device__ __align__(16) float g_idf[M_CAP];    // float(id) if s<nr-1 else -1
__device__ int  g_block_cnt[NB];
__device__ int  g_block_pfx[NB];                // exclusive prefix of counts
__device__ int  g_num_runs;

// ---------------------------------------------------------------------------
// Kernel 1: count run-starts per block + prefill g_idf with -1.
// ---------------------------------------------------------------------------
__global__ __launch_bounds__(BLK) void k_count(const int* __restrict__ ids) {
    const int b  = blockIdx.x;
    const int t  = threadIdx.x;
    const int i0 = b * EPB + t * IPT;

    // prefill g_idf slice (stale-replay protection); 256 floats per block
    g_idf[b * BLK + t] = -1.0f;
    if (b == 0 && t == 0) g_idf[M_CAP - 1] = -1.0f;

    const int4* p = reinterpret_cast<const int4*>(ids + i0);
    int4 a0 = p[0], a1 = p[1], a2 = p[2], a3 = p[3];
    int v[IPT] = {a0.x, a0.y, a0.z, a0.w,
                  a1.x, a1.y, a1.z, a1.w,
                  a2.x, a2.y, a2.z, a2.w,
                  a3.x, a3.y, a3.z, a3.w};

    int prev = (i0 == 0) ? ~v[0] : ids[i0 - 1];
    int cnt = 0;
#pragma unroll
    for (int j = 0; j < IPT; j++) {
        cnt += (v[j] != prev);
        prev = v[j];
    }

    __shared__ int sh[BLK / 32];
#pragma unroll
    for (int off = 16; off > 0; off >>= 1)
        cnt += __shfl_down_sync(0xFFFFFFFFu, cnt, off);
    if ((t & 31) == 0) sh[t >> 5] = cnt;
    __syncthreads();
    if (t < BLK / 32) {
        int s = sh[t];
#pragma unroll
        for (int off = (BLK / 64); off > 0; off >>= 1)
            s += __shfl_down_sync(0xFFu, s, off);
        if (t == 0) g_block_cnt[b] = s;
    }
}

// ---------------------------------------------------------------------------
// Kernel 2: single-block exclusive scan of NB block counts (shuffle-based).
// ---------------------------------------------------------------------------
__global__ __launch_bounds__(NB) void k_scan() {
    const int t    = threadIdx.x;
    const int lane = t & 31;
    const int wid  = t >> 5;
    const int v = g_block_cnt[t];

    int s = v;
#pragma unroll
    for (int off = 1; off < 32; off <<= 1) {
        int x = __shfl_up_sync(0xFFFFFFFFu, s, off);
        if (lane >= off) s += x;
    }

    __shared__ int ws[32];
    if (lane == 31) ws[wid] = s;
    __syncthreads();
    if (wid == 0) {
        int x = ws[lane];
        int y = x;
#pragma unroll
        for (int off = 1; off < 32; off <<= 1) {
            int z = __shfl_up_sync(0xFFFFFFFFu, y, off);
            if (lane >= off) y += z;
        }
        ws[lane] = y - x;
    }
    __syncthreads();

    const int incl = s + ws[wid];
    g_block_pfx[t] = incl - v;
    if (t == NB - 1) g_num_runs = incl;
}

// ---------------------------------------------------------------------------
// Kernel 3: recompute starts, block-local exclusive scan, scatter SoA.
// ---------------------------------------------------------------------------
__global__ __launch_bounds__(BLK) void k_starts(const int* __restrict__ ids) {
    const int b  = blockIdx.x;
    const int t  = threadIdx.x;
    const int i0 = b * EPB + t * IPT;
    const int nr1 = g_num_runs - 1;

    const int4* p = reinterpret_cast<const int4*>(ids + i0);
    int4 a0 = p[0], a1 = p[1], a2 = p[2], a3 = p[3];
    int v[IPT] = {a0.x, a0.y, a0.z, a0.w,
                  a1.x, a1.y, a1.z, a1.w,
                  a2.x, a2.y, a2.z, a2.w,
                  a3.x, a3.y, a3.z, a3.w};

    int first_prev = (i0 == 0) ? ~v[0] : ids[i0 - 1];

    int prev = first_prev;
    int cnt = 0;
#pragma unroll
    for (int j = 0; j < IPT; j++) {
        cnt += (v[j] != prev);
        prev = v[j];
    }

    const int lane = t & 31;
    const int wid  = t >> 5;
    int s = cnt;
#pragma unroll
    for (int off = 1; off < 32; off <<= 1) {
        int x = __shfl_up_sync(0xFFFFFFFFu, s, off);
        if (lane >= off) s += x;
    }
    __shared__ int ws[BLK / 32];
    if (lane == 31) ws[wid] = s;
    __syncthreads();
    if (wid == 0 && lane < BLK / 32) {
        int x = ws[lane];
        int y = x;
#pragma unroll
        for (int off = 1; off < BLK / 32; off <<= 1) {
            int z = __shfl_up_sync(0xFFu, y, off);
            if (lane >= off) y += z;
        }
        ws[lane] = y - x;
    }
    __syncthreads();
    int rank = g_block_pfx[b] + ws[wid] + (s - cnt);

    prev = first_prev;
#pragma unroll
    for (int j = 0; j < IPT; j++) {
        if (v[j] != prev) {
            g_start[rank] = i0 + j;
            g_idf[rank]   = (rank < nr1) ? (float)v[j] : -1.0f;
            rank++;
        }
        prev = v[j];
    }
}

// ---------------------------------------------------------------------------
// Kernel 4: one WARP per aligned 128-float output window, branch-free body.
// Flat layout (float32): out[0..M_CAP) = run_ids, then padded [M_CAP x 128].
// Since M_CAP % 128 == 1:
//   - windows 0..2047 : pure run_ids  -> aligned float4 copy of g_idf
//   - window  w>=2048 : col 127 of row A=w-2049 (lane 0 head, blended
//     branch-free), then cols 0..126 of row B=A+1. Window 2048: A=-1,
//     head = run_ids[M_CAP-1] which is always -1 (nr <= NUM_IDS < M_CAP).
// ---------------------------------------------------------------------------
__global__ __launch_bounds__(256) void k_fill(const float* __restrict__ feats,
                                              float* __restrict__ out) {
    if (blockIdx.x == 0 && threadIdx.x == 0)
        out[OUT_TOTAL - 1] = 0.0f;                // tail float (always padding)

    const int warp = blockIdx.x * 8 + (threadIdx.x >> 5);
    const int lane = threadIdx.x & 31;
    if (warp >= NW) return;

    float4 v;

    if (warp < 2048) {
        // ---- run_ids region: straight vectorized copy ----
        v = reinterpret_cast<const float4*>(g_idf)[warp * 32 + lane];
    } else {
        // ---- padded region ----
        const int nr1 = g_num_runs - 1;
        const int A   = warp - 2049;              // -1 for warp == 2048

        int idx = A + (lane < 2 ? lane : 2);      // lanes need A, A+1, A+2
        idx = idx < 0 ? 0 : idx;
        idx = idx > nr1 ? nr1 : idx;              // clamp into written region
        const int m  = g_start[idx];
        const int sA = __shfl_sync(0xFFFFFFFFu, m, 0);
        const int sB = __shfl_sync(0xFFFFFFFFu, m, 1);
        const int sC = __shfl_sync(0xFFFFFFFFu, m, 2);
        const bool vA = ((unsigned)A       < (unsigned)nr1);
        const bool vB = ((unsigned)(A + 1) < (unsigned)nr1);
        const int lenA = sB - sA;
        const int lenB = sC - sB;

        const int  c0  = 4 * lane - 1;            // col of element 0 (-1 head)
        const bool l0  = (lane == 0);

        // element 0: lane 0 -> col 127 of row A; others -> col c0 of row B
        const int  a0 = l0 ? (sA + 127) : (sB + c0);
        const bool p0 = l0 ? (vA && lenA > 127) : (vB && c0 < lenB);
        float x0 = (l0 && A < 0) ? -1.0f : 0.0f;
        if (p0) x0 = feats[a0];

        float x1 = 0.0f, x2 = 0.0f, x3 = 0.0f;
        const int base = sB + c0;
        if (vB && c0 + 1 < lenB) x1 = feats[base + 1];
        if (vB && c0 + 2 < lenB) x2 = feats[base + 2];
        if (vB && c0 + 3 < lenB) x3 = feats[base + 3];

        v = make_float4(x0, x1, x2, x3);
    }

    // streaming store: output exceeds L2 and is never re-read
    __stcs(reinterpret_cast<float4*>(out) + (size_t)warp * 32 + lane, v);
}

// ---------------------------------------------------------------------------
extern "C" void kernel_launch(void* const* d_in, const int* in_sizes, int n_in,
                              void* d_out, int out_size) {
    const int*   ids   = (const int*)d_in[0];
    const float* feats = (const float*)d_in[1];
    float*       out   = (float*)d_out;

    k_count <<<NB, BLK>>>(ids);
    k_scan  <<<1, NB>>>();
    k_starts<<<NB, BLK>>>(ids);

    const int fill_blocks = (NW + 7) / 8;         // 8 warps per block
    k_fill  <<<fill_blocks, 256>>>(feats, out);
}

// round 5
// speedup vs baseline: 1.1540x; 1.1540x over previous
#include <cuda_runtime.h>
#include <stdint.h>

// Problem constants (match reference)
#define N_ELEMS   4194304        // total elements
#define NUM_IDS   262144
#define M_CAP     (NUM_IDS + 1)  // 262145 output rows
#define L_CAP     128
#define OUT_TOTAL (M_CAP + M_CAP * L_CAP)   // 33,816,705 floats
#define NW        264193         // full 128-float windows (NW*128 = OUT_TOTAL-1)
#define WPW       4              // windows per warp
#define NWG       66049          // warp-groups = ceil(NW / WPW)

// Scan decomposition: 1024 blocks * 4096 elems; 256 threads * 16 items/thread
#define NB        1024
#define EPB       4096
#define BLK       256
#define IPT       16

// Scratch (device globals: no allocation allowed) — SoA layout
__device__ __align__(16) int   g_start[M_CAP];  // start element index of run s
__device__ __align__(16) float g_idf[M_CAP];    // float(id) if s<nr-1 else -1
__device__ int  g_block_cnt[NB];
__device__ int  g_block_pfx[NB];                // exclusive prefix of counts
__device__ int  g_num_runs;

// ---------------------------------------------------------------------------
// Kernel 1: count run-starts per block + prefill g_idf with -1.
// ---------------------------------------------------------------------------
__global__ __launch_bounds__(BLK) void k_count(const int* __restrict__ ids) {
    const int b  = blockIdx.x;
    const int t  = threadIdx.x;
    const int i0 = b * EPB + t * IPT;

    // prefill g_idf slice (stale-replay protection); 256 floats per block
    g_idf[b * BLK + t] = -1.0f;
    if (b == 0 && t == 0) g_idf[M_CAP - 1] = -1.0f;

    const int4* p = reinterpret_cast<const int4*>(ids + i0);
    int4 a0 = p[0], a1 = p[1], a2 = p[2], a3 = p[3];
    int v[IPT] = {a0.x, a0.y, a0.z, a0.w,
                  a1.x, a1.y, a1.z, a1.w,
                  a2.x, a2.y, a2.z, a2.w,
                  a3.x, a3.y, a3.z, a3.w};

    int prev = (i0 == 0) ? ~v[0] : ids[i0 - 1];
    int cnt = 0;
#pragma unroll
    for (int j = 0; j < IPT; j++) {
        cnt += (v[j] != prev);
        prev = v[j];
    }

    __shared__ int sh[BLK / 32];
#pragma unroll
    for (int off = 16; off > 0; off >>= 1)
        cnt += __shfl_down_sync(0xFFFFFFFFu, cnt, off);
    if ((t & 31) == 0) sh[t >> 5] = cnt;
    __syncthreads();
    if (t < BLK / 32) {
        int s = sh[t];
#pragma unroll
        for (int off = (BLK / 64); off > 0; off >>= 1)
            s += __shfl_down_sync(0xFFu, s, off);
        if (t == 0) g_block_cnt[b] = s;
    }
}

// ---------------------------------------------------------------------------
// Kernel 2: single-block exclusive scan of NB block counts (shuffle-based).
// ---------------------------------------------------------------------------
__global__ __launch_bounds__(NB) void k_scan() {
    const int t    = threadIdx.x;
    const int lane = t & 31;
    const int wid  = t >> 5;
    const int v = g_block_cnt[t];

    int s = v;
#pragma unroll
    for (int off = 1; off < 32; off <<= 1) {
        int x = __shfl_up_sync(0xFFFFFFFFu, s, off);
        if (lane >= off) s += x;
    }

    __shared__ int ws[32];
    if (lane == 31) ws[wid] = s;
    __syncthreads();
    if (wid == 0) {
        int x = ws[lane];
        int y = x;
#pragma unroll
        for (int off = 1; off < 32; off <<= 1) {
            int z = __shfl_up_sync(0xFFFFFFFFu, y, off);
            if (lane >= off) y += z;
        }
        ws[lane] = y - x;
    }
    __syncthreads();

    const int incl = s + ws[wid];
    g_block_pfx[t] = incl - v;
    if (t == NB - 1) g_num_runs = incl;
}

// ---------------------------------------------------------------------------
// Kernel 3: recompute starts, block-local exclusive scan, scatter SoA.
// ---------------------------------------------------------------------------
__global__ __launch_bounds__(BLK) void k_starts(const int* __restrict__ ids) {
    const int b  = blockIdx.x;
    const int t  = threadIdx.x;
    const int i0 = b * EPB + t * IPT;
    const int nr1 = g_num_runs - 1;

    const int4* p = reinterpret_cast<const int4*>(ids + i0);
    int4 a0 = p[0], a1 = p[1], a2 = p[2], a3 = p[3];
    int v[IPT] = {a0.x, a0.y, a0.z, a0.w,
                  a1.x, a1.y, a1.z, a1.w,
                  a2.x, a2.y, a2.z, a2.w,
                  a3.x, a3.y, a3.z, a3.w};

    int first_prev = (i0 == 0) ? ~v[0] : ids[i0 - 1];

    int prev = first_prev;
    int cnt = 0;
#pragma unroll
    for (int j = 0; j < IPT; j++) {
        cnt += (v[j] != prev);
        prev = v[j];
    }

    const int lane = t & 31;
    const int wid  = t >> 5;
    int s = cnt;
#pragma unroll
    for (int off = 1; off < 32; off <<= 1) {
        int x = __shfl_up_sync(0xFFFFFFFFu, s, off);
        if (lane >= off) s += x;
    }
    __shared__ int ws[BLK / 32];
    if (lane == 31) ws[wid] = s;
    __syncthreads();
    if (wid == 0 && lane < BLK / 32) {
        int x = ws[lane];
        int y = x;
#pragma unroll
        for (int off = 1; off < BLK / 32; off <<= 1) {
            int z = __shfl_up_sync(0xFFu, y, off);
            if (lane >= off) y += z;
        }
        ws[lane] = y - x;
    }
    __syncthreads();
    int rank = g_block_pfx[b] + ws[wid] + (s - cnt);

    prev = first_prev;
#pragma unroll
    for (int j = 0; j < IPT; j++) {
        if (v[j] != prev) {
            g_start[rank] = i0 + j;
            g_idf[rank]   = (rank < nr1) ? (float)v[j] : -1.0f;
            rank++;
        }
        prev = v[j];
    }
}

// ---------------------------------------------------------------------------
// Kernel 4: one WARP per FOUR consecutive 128-float output windows.
// Flat layout (float32): out[0..M_CAP) = run_ids, then padded [M_CAP x 128].
// M_CAP % 128 == 1, so window w>=2048 = col 127 of row A=w-2049 then cols
// 0..126 of row A+1 (window 2048: A=-1, head is run_ids[M_CAP-1] == -1).
// The region boundary (2048) is 4-aligned: each warp-group is purely
// run_ids (W < 512) or purely padded. A padded group's 4 windows share
// rows A0..A0+4 -> ONE coalesced metadata load of g_start[A0..A0+5]
// (lanes 0..5), then 4 independent feats-load chains (MLP = 4).
// ---------------------------------------------------------------------------
__global__ __launch_bounds__(256) void k_fill(const float* __restrict__ feats,
                                              float* __restrict__ out) {
    if (blockIdx.x == 0 && threadIdx.x == 0)
        out[OUT_TOTAL - 1] = 0.0f;                // tail float (always padding)

    const int W    = blockIdx.x * 8 + (threadIdx.x >> 5);   // warp-group id
    const int lane = threadIdx.x & 31;
    if (W >= NWG) return;
    const int w0 = W * WPW;                        // first window of group

    if (W < 512) {
        // ---- run_ids region: 4 independent vectorized copies ----
        float4 r[WPW];
#pragma unroll
        for (int k = 0; k < WPW; k++)
            r[k] = reinterpret_cast<const float4*>(g_idf)[(w0 + k) * 32 + lane];
#pragma unroll
        for (int k = 0; k < WPW; k++)
            __stcs(reinterpret_cast<float4*>(out) + (size_t)(w0 + k) * 32 + lane,
                   r[k]);
        return;
    }

    // ---- padded region ----
    const int nr1 = g_num_runs - 1;
    const int A0  = w0 - 2049;                     // head row of window 0

    // one coalesced metadata load: g_start[A0 .. A0+5]
    int mv = 0;
    if (lane < 6) {
        int idx = A0 + lane;
        idx = idx < 0 ? 0 : idx;
        idx = idx > nr1 ? nr1 : idx;
        mv = g_start[idx];
    }
    int m[6];
#pragma unroll
    for (int j = 0; j < 6; j++) m[j] = __shfl_sync(0xFFFFFFFFu, mv, j);

    const int  c0 = 4 * lane - 1;                  // col of element 0
    const bool l0 = (lane == 0);

    float4 r[WPW];
    bool   ok[WPW];
#pragma unroll
    for (int k = 0; k < WPW; k++) {
        const int w = w0 + k;
        ok[k] = (w < NW);
        const int A    = A0 + k;
        const int sA   = m[k];
        const int sB   = m[k + 1];
        const int sC   = m[k + 2];
        const bool vA  = ((unsigned)A       < (unsigned)nr1);
        const bool vB  = ((unsigned)(A + 1) < (unsigned)nr1);
        const int lenA = sB - sA;
        const int lenB = sC - sB;

        // element 0: lane 0 -> col 127 of row A; others -> col c0 of row A+1
        const int  a0 = l0 ? (sA + 127) : (sB + c0);
        const bool p0 = l0 ? (vA && lenA > 127) : (vB && c0 < lenB);
        float x0 = (l0 && A < 0) ? -1.0f : 0.0f;
        if (ok[k] && p0) x0 = feats[a0];

        float x1 = 0.0f, x2 = 0.0f, x3 = 0.0f;
        const int base = sB + c0;
        if (ok[k] && vB && c0 + 1 < lenB) x1 = feats[base + 1];
        if (ok[k] && vB && c0 + 2 < lenB) x2 = feats[base + 2];
        if (ok[k] && vB && c0 + 3 < lenB) x3 = feats[base + 3];

        r[k] = make_float4(x0, x1, x2, x3);
    }

#pragma unroll
    for (int k = 0; k < WPW; k++)
        if (ok[k])
            __stcs(reinterpret_cast<float4*>(out) + (size_t)(w0 + k) * 32 + lane,
                   r[k]);
}

// ---------------------------------------------------------------------------
extern "C" void kernel_launch(void* const* d_in, const int* in_sizes, int n_in,
                              void* d_out, int out_size) {
    const int*   ids   = (const int*)d_in[0];
    const float* feats = (const float*)d_in[1];
    float*       out   = (float*)d_out;

    k_count <<<NB, BLK>>>(ids);
    k_scan  <<<1, NB>>>();
    k_starts<<<NB, BLK>>>(ids);

    const int fill_blocks = (NWG + 7) / 8;        // 8 warp-groups per block
    k_fill  <<<fill_blocks, 256>>>(feats, out);
}

// round 6
// speedup vs baseline: 1.1577x; 1.0033x over previous
#include <cuda_runtime.h>
#include <stdint.h>

// Problem constants (match reference)
#define N_ELEMS   4194304        // total elements
#define NUM_IDS   262144
#define M_CAP     (NUM_IDS + 1)  // 262145 output rows
#define L_CAP     128
#define OUT_TOTAL (M_CAP + M_CAP * L_CAP)   // 33,816,705 floats
#define NW        264193         // full 128-float windows (NW*128 = OUT_TOTAL-1)
#define WPW       8              // windows per warp
#define NWG       33025          // warp-groups = ceil(NW / WPW)

// Scan decomposition: 1024 blocks * 4096 elems; 256 threads * 16 items/thread
#define NB        1024
#define EPB       4096
#define BLK       256
#define IPT       16

// Descriptor states for decoupled lookback (packed: state<<32 | value)
#define ST_AGG    1ull
#define ST_PFX    2ull

// Scratch (device globals: no allocation allowed) — SoA layout
__device__ __align__(16) int   g_start[M_CAP];  // start element index of run s
__device__ __align__(16) float g_idf[M_CAP];    // float(id) for written runs
__device__ unsigned long long  g_desc[NB];      // lookback descriptors
                                                // zero-init; k_fill re-zeros
__device__ int g_num_runs;

// ---------------------------------------------------------------------------
// Kernel 1 (fused): single-pass count + decoupled-lookback scan + scatter.
// One read of ids. Blocks publish AGG immediately, then lookback (warp 0,
// 32 predecessors per iteration, __reduce_add_sync), then publish PREFIX.
// Safe: predecessors always have lower block ids -> dispatched no later.
// g_desc must be all-zero on entry (guaranteed: zero-init + k_fill resets).
// ---------------------------------------------------------------------------
__global__ __launch_bounds__(BLK) void k_scan_scatter(const int* __restrict__ ids) {
    const int b  = blockIdx.x;
    const int t  = threadIdx.x;
    const int i0 = b * EPB + t * IPT;

    const int4* p = reinterpret_cast<const int4*>(ids + i0);
    int4 a0 = p[0], a1 = p[1], a2 = p[2], a3 = p[3];
    int v[IPT] = {a0.x, a0.y, a0.z, a0.w,
                  a1.x, a1.y, a1.z, a1.w,
                  a2.x, a2.y, a2.z, a2.w,
                  a3.x, a3.y, a3.z, a3.w};

    const int first_prev = (i0 == 0) ? ~v[0] : ids[i0 - 1];

    int prev = first_prev;
    int cnt = 0;
#pragma unroll
    for (int j = 0; j < IPT; j++) {
        cnt += (v[j] != prev);
        prev = v[j];
    }

    // --- block-wide exclusive scan of per-thread counts (2-level shuffle) ---
    const int lane = t & 31;
    const int wid  = t >> 5;
    int s = cnt;
#pragma unroll
    for (int off = 1; off < 32; off <<= 1) {
        int x = __shfl_up_sync(0xFFFFFFFFu, s, off);
        if (lane >= off) s += x;
    }
    __shared__ int ws[BLK / 32];
    __shared__ int sTotal;
    __shared__ int sBase;
    if (lane == 31) ws[wid] = s;
    __syncthreads();
    if (wid == 0 && lane < BLK / 32) {
        int x = ws[lane];
        int y = x;
#pragma unroll
        for (int off = 1; off < BLK / 32; off <<= 1) {
            int z = __shfl_up_sync(0xFFu, y, off);
            if (lane >= off) y += z;
        }
        ws[lane] = y - x;                       // exclusive warp base
        if (lane == BLK / 32 - 1) sTotal = y;   // block total
    }
    __syncthreads();
    const int texcl       = ws[wid] + (s - cnt);
    const int block_total = sTotal;

    // --- publish aggregate (block 0 publishes prefix directly) ---
    if (t == 0) {
        if (b == 0) {
            g_desc[0] = (ST_PFX << 32) | (unsigned)block_total;
            sBase = 0;
        } else {
            g_desc[b] = (ST_AGG << 32) | (unsigned)block_total;
        }
    }

    // --- decoupled lookback (warp 0) ---
    if (b > 0 && t < 32) {
        unsigned running = 0;
        int look = b - 1;
        for (;;) {
            const int idx = look - t;
            unsigned long long d;
            if (idx >= 0) {
                do {
                    d = *(volatile const unsigned long long*)(g_desc + idx);
                } while ((d >> 32) == 0ull);
            } else {
                d = (ST_PFX << 32);             // virtual prefix 0
            }
            const unsigned st  = (unsigned)(d >> 32);
            const unsigned val = (unsigned)d;
            const unsigned pmask = __ballot_sync(0xFFFFFFFFu, st == 2u);
            if (pmask) {
                const int pl = __ffs(pmask) - 1;   // closest prefix
                running += __reduce_add_sync(0xFFFFFFFFu, (t <= pl) ? val : 0u);
                break;
            }
            running += __reduce_add_sync(0xFFFFFFFFu, val);
            look -= 32;
        }
        if (t == 0) {
            sBase = (int)running;
            g_desc[b] = (ST_PFX << 32) | (unsigned)(running + block_total);
        }
    }
    __syncthreads();
    const int base = sBase;

    if (b == NB - 1 && t == 0) g_num_runs = base + block_total;

    // --- scatter run starts + ids (SoA) ---
    int rank = base + texcl;
    prev = first_prev;
#pragma unroll
    for (int j = 0; j < IPT; j++) {
        if (v[j] != prev) {
            g_start[rank] = i0 + j;
            g_idf[rank]   = (float)v[j];
            rank++;
        }
        prev = v[j];
    }
}

// ---------------------------------------------------------------------------
// Kernel 2: one WARP per EIGHT consecutive 128-float output windows.
// Flat layout (float32): out[0..M_CAP) = run_ids, then padded [M_CAP x 128].
// M_CAP % 128 == 1, so window w>=2048 = col 127 of row A=w-2049 then cols
// 0..126 of row A+1 (window 2048: A=-1, head = run_ids[M_CAP-1] == -1).
// Boundary (2048) is 8-aligned: each warp-group is purely run_ids (W < 256)
// or purely padded. A padded group's 8 windows share rows A0..A0+8 -> ONE
// coalesced metadata load g_start[A0..A0+9] (lanes 0..9), then the 8 windows
// run as two register-friendly half-batches of 4 (stores are fire-and-forget,
// so batch-2 loads overlap batch-1 completion).
// Also resets g_desc to zero for the next graph replay (block 0).
// ---------------------------------------------------------------------------
__global__ __launch_bounds__(256) void k_fill(const float* __restrict__ feats,
                                              float* __restrict__ out) {
    if (blockIdx.x == 0) {
#pragma unroll
        for (int j = 0; j < 4; j++)
            g_desc[threadIdx.x * 4 + j] = 0ull;   // 256*4 = NB entries
        if (threadIdx.x == 0)
            out[OUT_TOTAL - 1] = 0.0f;            // tail float (padding)
    }

    const int W    = blockIdx.x * 8 + (threadIdx.x >> 5);   // warp-group id
    const int lane = threadIdx.x & 31;
    if (W >= NWG) return;
    const int w0  = W * WPW;
    const int nr1 = g_num_runs - 1;               // runs actually emitted

    if (W < 256) {
        // ---- run_ids region: 8 vectorized copies with tail masking ----
#pragma unroll
        for (int k = 0; k < WPW; k++) {
            float4 r = reinterpret_cast<const float4*>(g_idf)[(w0 + k) * 32 + lane];
            const int e = (w0 + k) * 128 + lane * 4;
            r.x = (e     < nr1) ? r.x : -1.0f;
            r.y = (e + 1 < nr1) ? r.y : -1.0f;
            r.z = (e + 2 < nr1) ? r.z : -1.0f;
            r.w = (e + 3 < nr1) ? r.w : -1.0f;
            __stcs(reinterpret_cast<float4*>(out) + (size_t)(w0 + k) * 32 + lane, r);
        }
        return;
    }

    // ---- padded region ----
    const int A0 = w0 - 2049;                     // head row of window 0

    // one coalesced metadata load: g_start[A0 .. A0+9]
    int mv = 0;
    if (lane < WPW + 2) {
        int idx = A0 + lane;
        idx = idx < 0 ? 0 : idx;
        idx = idx > nr1 ? nr1 : idx;              // clamp into written region
        mv = g_start[idx];
    }
    int m[WPW + 2];
#pragma unroll
    for (int j = 0; j < WPW + 2; j++) m[j] = __shfl_sync(0xFFFFFFFFu, mv, j);

    const int  c0 = 4 * lane - 1;                 // col of element 0
    const bool l0 = (lane == 0);

#pragma unroll
    for (int h = 0; h < 2; h++) {
        float4 r[4];
        bool   ok[4];
#pragma unroll
        for (int k2 = 0; k2 < 4; k2++) {
            const int k = h * 4 + k2;
            const int w = w0 + k;
            ok[k2] = (w < NW);
            const int A    = A0 + k;
            const int sA   = m[k];
            const int sB   = m[k + 1];
            const int sC   = m[k + 2];
            const bool vA  = ((unsigned)A       < (unsigned)nr1);
            const bool vB  = ((unsigned)(A + 1) < (unsigned)nr1);
            const int lenA = sB - sA;
            const int lenB = sC - sB;

            // element 0: lane 0 -> col 127 of row A; others -> col c0 of A+1
            const int  a0 = l0 ? (sA + 127) : (sB + c0);
            const bool p0 = l0 ? (vA && lenA > 127) : (vB && c0 < lenB);
            float x0 = (l0 && A < 0) ? -1.0f : 0.0f;
            if (ok[k2] && p0) x0 = feats[a0];

            float x1 = 0.0f, x2 = 0.0f, x3 = 0.0f;
            const int base = sB + c0;
            if (ok[k2] && vB && c0 + 1 < lenB) x1 = feats[base + 1];
            if (ok[k2] && vB && c0 + 2 < lenB) x2 = feats[base + 2];
            if (ok[k2] && vB && c0 + 3 < lenB) x3 = feats[base + 3];

            r[k2] = make_float4(x0, x1, x2, x3);
        }
#pragma unroll
        for (int k2 = 0; k2 < 4; k2++)
            if (ok[k2])
                __stcs(reinterpret_cast<float4*>(out) +
                           (size_t)(w0 + h * 4 + k2) * 32 + lane,
                       r[k2]);
    }
}

// ---------------------------------------------------------------------------
extern "C" void kernel_launch(void* const* d_in, const int* in_sizes, int n_in,
                              void* d_out, int out_size) {
    const int*   ids   = (const int*)d_in[0];
    const float* feats = (const float*)d_in[1];
    float*       out   = (float*)d_out;

    k_scan_scatter<<<NB, BLK>>>(ids);

    const int fill_blocks = (NWG + 7) / 8;        // 8 warp-groups per block
    k_fill<<<fill_blocks, 256>>>(feats, out);
}